// round 11
// baseline (speedup 1.0000x reference)
#include <cuda_runtime.h>
#include <cstdint>

#define Bn 16
#define Tn 256
#define Cn 6
#define En 512
#define Hn 8
#define HD 64
#define NTOK (Bn*Tn*Cn)      // 24576
#define NHEADS (Bn*Hn*Cn)    // 768

// ---- device-global scratch (no allocations allowed) ----
// g_xr, g_wr, g_y hold k-interleaved (perfect-shuffle per 8-block) tf32 data.
__device__ float g_q[(size_t)NHEADS * Tn * HD];
__device__ float g_k[(size_t)NHEADS * Tn * HD];
__device__ float g_v[(size_t)NHEADS * Tn * HD];
__device__ float g_y[(size_t)NTOK * En];
__device__ float g_xr[(size_t)NTOK * En];
__device__ float g_wr[(size_t)4 * En * En];

// ---------------------------------------------------------------------------
__device__ __forceinline__ float tf32r(float x) {
    uint32_t u;
    asm("cvt.rna.tf32.f32 %0, %1;" : "=r"(u) : "f"(x));
    return __uint_as_float(u);
}

__device__ __forceinline__ void cpasync16(void* smem_dst, const void* gsrc) {
    uint32_t s = (uint32_t)__cvta_generic_to_shared(smem_dst);
    asm volatile("cp.async.ca.shared.global [%0], [%1], 16;\n" :: "r"(s), "l"(gsrc));
}

__device__ __forceinline__ void mma_tf32(float c[4], const uint32_t a[4], const uint32_t b[2]) {
    asm volatile(
        "mma.sync.aligned.m16n8k8.row.col.f32.tf32.tf32.f32 "
        "{%0,%1,%2,%3}, {%4,%5,%6,%7}, {%8,%9}, {%0,%1,%2,%3};"
        : "+f"(c[0]), "+f"(c[1]), "+f"(c[2]), "+f"(c[3])
        : "r"(a[0]), "r"(a[1]), "r"(a[2]), "r"(a[3]), "r"(b[0]), "r"(b[1]));
}

// ---------------------------------------------------------------------------
// Prepass: round to tf32 AND perfect-shuffle each 8-float k-block:
//   out[8b + 0..7] = in[8b + {0,4,1,5,2,6,3,7}]
// so that GEMM fragment pairs (k, k+4) are adjacent -> LDS.64 fragment loads.
// ---------------------------------------------------------------------------
__device__ __forceinline__ void shuffle_store8(float* dst, float4 lo, float4 hi) {
    float4 o0, o1;
    o0.x = tf32r(lo.x); o0.y = tf32r(hi.x); o0.z = tf32r(lo.y); o0.w = tf32r(hi.y);
    o1.x = tf32r(lo.z); o1.y = tf32r(hi.z); o1.z = tf32r(lo.w); o1.w = tf32r(hi.w);
    *(float4*)dst       = o0;
    *(float4*)(dst + 4) = o1;
}

__global__ void round_x_kernel(const float* __restrict__ x) {
    int i = blockIdx.x * 256 + threadIdx.x;            // 8-block index
    float4 lo = ((const float4*)x)[i * 2];
    float4 hi = ((const float4*)x)[i * 2 + 1];
    shuffle_store8(g_xr + (size_t)i * 8, lo, hi);
}

__global__ void round_w_kernel(const float* __restrict__ Wq, const float* __restrict__ Wk,
                               const float* __restrict__ Wv, const float* __restrict__ Wp) {
    int i = blockIdx.x * 256 + threadIdx.x;            // 8-block index, 4*32768 total
    int w = i >> 15;
    int off = i & 32767;
    const float* src = (w == 0) ? Wq : (w == 1) ? Wk : (w == 2) ? Wv : Wp;
    float4 lo = ((const float4*)src)[off * 2];
    float4 hi = ((const float4*)src)[off * 2 + 1];
    shuffle_store8(g_wr + (size_t)i * 8, lo, hi);
}

// ---------------------------------------------------------------------------
// tf32 MMA GEMM core on k-interleaved operands.
// 128x128 CTA tile, 8 warps (2M x 4N), warp tile 64x32, BK=16, double-buffered
// cp.async. Smem row stride 24 floats (== 8 mod 32): every LDS.64 fragment
// access phase covers all 32 banks exactly once.
// ---------------------------------------------------------------------------
#define SSTR 24
#define BK   16

__device__ __forceinline__ void load_tile(float* As, float* Bs,
                                          const float* gA, const float* gB, int k0) {
    const int tid = threadIdx.x;
    #pragma unroll
    for (int it = 0; it < 2; it++) {
        int idx = it * 256 + tid;          // 0..511
        int m   = idx >> 2;
        int kc  = (idx & 3) * 4;
        cpasync16(As + m * SSTR + kc, gA + (size_t)m * En + k0 + kc);
        cpasync16(Bs + m * SSTR + kc, gB + (size_t)m * En + k0 + kc);
    }
    asm volatile("cp.async.commit_group;\n" ::);
}

__device__ __forceinline__ void compute_tile(const float* As, const float* Bs,
                                             float acc[4][4][4],
                                             int wm, int wn, int gr, int ctl) {
    #pragma unroll
    for (int g2 = 0; g2 < 2; g2++) {       // two 8-k subgroups of BK=16
        const int ko = g2 * 8 + 2 * ctl;
        uint32_t a[4][4], b[4][2];
        #pragma unroll
        for (int mi = 0; mi < 4; mi++) {
            const float* p = As + (wm * 64 + mi * 16 + gr) * SSTR + ko;
            float2 lo = *(const float2*)p;
            float2 hi = *(const float2*)(p + 8 * SSTR);
            a[mi][0] = __float_as_uint(lo.x);
            a[mi][2] = __float_as_uint(lo.y);
            a[mi][1] = __float_as_uint(hi.x);
            a[mi][3] = __float_as_uint(hi.y);
        }
        #pragma unroll
        for (int ni = 0; ni < 4; ni++) {
            const float* p = Bs + (wn * 32 + ni * 8 + gr) * SSTR + ko;
            float2 v = *(const float2*)p;
            b[ni][0] = __float_as_uint(v.x);
            b[ni][1] = __float_as_uint(v.y);
        }
        #pragma unroll
        for (int mi = 0; mi < 4; mi++)
            #pragma unroll
            for (int ni = 0; ni < 4; ni++)
                mma_tf32(acc[mi][ni], a[mi], b[ni]);
    }
}

#define GEMM_MAINLOOP(gA, gB)                                          \
    load_tile(As[0], Bs[0], gA, gB, 0);                                \
    _Pragma("unroll 1")                                                \
    for (int kt = 0; kt < En / BK; kt++) {                             \
        if (kt + 1 < En / BK) {                                        \
            load_tile(As[(kt + 1) & 1], Bs[(kt + 1) & 1], gA, gB,      \
                      (kt + 1) * BK);                                  \
            asm volatile("cp.async.wait_group 1;\n" ::);               \
        } else {                                                       \
            asm volatile("cp.async.wait_group 0;\n" ::);               \
        }                                                              \
        __syncthreads();                                               \
        compute_tile(As[kt & 1], Bs[kt & 1], acc, wm, wn, gr, ctl);    \
        __syncthreads();                                               \
    }

// ---------------------------------------------------------------------------
// QKV: y = x @ W^T + b, scattered into per-head (b,h,c,t,d), tf32-rounded.
// grid = (192, 12): y [0,4)=Q, [4,8)=K, [8,12)=V
// ---------------------------------------------------------------------------
__global__ void __launch_bounds__(256, 2)
qkv_mma(const float* __restrict__ bq, const float* __restrict__ bk,
        const float* __restrict__ bv)
{
    __shared__ float As[2][128 * SSTR];
    __shared__ float Bs[2][128 * SSTR];

    const int tid = threadIdx.x, lane = tid & 31, warp = tid >> 5;
    const int wm = warp & 1, wn = warp >> 1;
    const int gr = lane >> 2, ctl = lane & 3;

    const int m0 = blockIdx.x * 128;
    const int mm = blockIdx.y >> 2;
    const int f0 = (blockIdx.y & 3) * 128;

    const float* gA = g_xr + (size_t)m0 * En;
    const float* gB = g_wr + (size_t)mm * En * En + (size_t)f0 * En;
    const float* bias = (mm == 0) ? bq : (mm == 1) ? bk : bv;
    float* gout = (mm == 0) ? g_q : (mm == 1) ? g_k : g_v;

    float acc[4][4][4];
    #pragma unroll
    for (int i = 0; i < 4; i++)
        #pragma unroll
        for (int j = 0; j < 4; j++)
            #pragma unroll
            for (int l = 0; l < 4; l++) acc[i][j][l] = 0.f;

    GEMM_MAINLOOP(gA, gB)

    const int fbase = f0 + wn * 32;
    #pragma unroll
    for (int mi = 0; mi < 4; mi++) {
        #pragma unroll
        for (int half = 0; half < 2; half++) {
            int r = m0 + wm * 64 + mi * 16 + gr + half * 8;
            int b = r / (Tn * Cn);
            int rem = r - b * (Tn * Cn);
            int t = rem / Cn;
            int cc = rem - t * Cn;
            #pragma unroll
            for (int ni = 0; ni < 4; ni++) {
                int f = fbase + ni * 8 + 2 * ctl;
                int h = f >> 6, d = f & 63;
                float2 o;
                o.x = tf32r(acc[mi][ni][half * 2 + 0] + bias[f]);
                o.y = tf32r(acc[mi][ni][half * 2 + 1] + bias[f + 1]);
                float* dst = gout + ((((size_t)b * Hn + h) * Cn + cc) * Tn + t) * HD + d;
                *(float2*)dst = o;
            }
        }
    }
}

// ---------------------------------------------------------------------------
// Output projection: out = g_y @ Wp^T + bp (both operands k-interleaved).
// ---------------------------------------------------------------------------
__global__ void __launch_bounds__(256, 2)
proj_mma(const float* __restrict__ bp, float* __restrict__ out)
{
    __shared__ float As[2][128 * SSTR];
    __shared__ float Bs[2][128 * SSTR];

    const int tid = threadIdx.x, lane = tid & 31, warp = tid >> 5;
    const int wm = warp & 1, wn = warp >> 1;
    const int gr = lane >> 2, ctl = lane & 3;

    const int m0 = blockIdx.x * 128;
    const int f0 = blockIdx.y * 128;

    const float* gA = g_y + (size_t)m0 * En;
    const float* gB = g_wr + (size_t)3 * En * En + (size_t)f0 * En;

    float acc[4][4][4];
    #pragma unroll
    for (int i = 0; i < 4; i++)
        #pragma unroll
        for (int j = 0; j < 4; j++)
            #pragma unroll
            for (int l = 0; l < 4; l++) acc[i][j][l] = 0.f;

    GEMM_MAINLOOP(gA, gB)

    #pragma unroll
    for (int mi = 0; mi < 4; mi++) {
        #pragma unroll
        for (int half = 0; half < 2; half++) {
            int r = m0 + wm * 64 + mi * 16 + gr + half * 8;
            #pragma unroll
            for (int ni = 0; ni < 4; ni++) {
                int col = f0 + wn * 32 + ni * 8 + 2 * ctl;
                float2 o;
                o.x = acc[mi][ni][half * 2 + 0] + bp[col];
                o.y = acc[mi][ni][half * 2 + 1] + bp[col + 1];
                *(float2*)(out + (size_t)r * En + col) = o;
            }
        }
    }
}

// ---------------------------------------------------------------------------
// MMA attention (round-4 structure + rna-rounded P; epilogue writes g_y in the
// k-interleaved order expected by proj_mma).
// 1 CTA per head, 8 warps; warp w owns query rows 32w..32w+31, does w/2+1 tiles.
// ---------------------------------------------------------------------------
#define KSTR 68
#define PSTR 72
#define ATTN_SMEM_BYTES ((2 * Tn * KSTR + 8 * 32 * PSTR) * 4)   // 212992

__global__ void __launch_bounds__(256, 1)
attn_kernel()
{
    extern __shared__ float smem[];
    float* Ks = smem;                  // [256][KSTR]
    float* Vs = smem + Tn * KSTR;      // [256][KSTR]

    const int hh = blockIdx.x;
    const int c  = hh % Cn;
    const int bh = hh / Cn;
    const int h  = bh % Hn;
    const int b  = bh / Hn;

    const float* qp = g_q + (size_t)hh * Tn * HD;
    const float* kp = g_k + (size_t)hh * Tn * HD;
    const float* vp = g_v + (size_t)hh * Tn * HD;

    const int tid  = threadIdx.x;
    const int lane = tid & 31, warp = tid >> 5;
    const int gr   = lane >> 2, ctl = lane & 3;

    float* Pw = smem + 2 * Tn * KSTR + warp * 32 * PSTR;  // [32][PSTR]

    // ---- load full K and V into smem ----
    #pragma unroll
    for (int it = 0; it < 16; it++) {
        int idx = it * 256 + tid;
        int row = idx >> 4;
        int c4  = (idx & 15) * 4;
        cpasync16(Ks + row * KSTR + c4, kp + row * HD + c4);
        cpasync16(Vs + row * KSTR + c4, vp + row * HD + c4);
    }
    asm volatile("cp.async.commit_group;\n" ::);

    const int r0 = warp * 32;
    asm volatile("cp.async.wait_group 0;\n" ::);
    __syncthreads();

    // ---- stage Q (scaled by exact 2^-3) into Pw, build A-fragments ----
    #pragma unroll
    for (int it = 0; it < 16; it++) {
        int idx = it * 32 + lane;
        int row = idx >> 4;
        int c4  = (idx & 15) * 4;
        float4 v4 = *(const float4*)(qp + (size_t)(r0 + row) * HD + c4);
        v4.x *= 0.125f; v4.y *= 0.125f; v4.z *= 0.125f; v4.w *= 0.125f;
        *(float4*)(Pw + row * PSTR + c4) = v4;
    }
    __syncwarp();

    uint32_t aq[2][8][4];
    #pragma unroll
    for (int mi = 0; mi < 2; mi++)
        #pragma unroll
        for (int ks = 0; ks < 8; ks++) {
            const float* p = Pw + (mi * 16 + gr) * PSTR + ks * 8 + ctl;
            aq[mi][ks][0] = __float_as_uint(p[0]);
            aq[mi][ks][1] = __float_as_uint(p[8 * PSTR]);
            aq[mi][ks][2] = __float_as_uint(p[4]);
            aq[mi][ks][3] = __float_as_uint(p[8 * PSTR + 4]);
        }

    float oacc[2][8][4];
    #pragma unroll
    for (int mi = 0; mi < 2; mi++)
        #pragma unroll
        for (int nt = 0; nt < 8; nt++)
            #pragma unroll
            for (int e = 0; e < 4; e++) oacc[mi][nt][e] = 0.f;
    float lsum[2][2] = {{0.f, 0.f}, {0.f, 0.f}};

    const int ntiles = (warp >> 1) + 1;

    #pragma unroll 1
    for (int jt = 0; jt < ntiles; jt++) {
        const int j0 = jt * 64;
        __syncwarp();

        #pragma unroll
        for (int hn = 0; hn < 2; hn++) {
            float s[2][4][4];
            #pragma unroll
            for (int mi = 0; mi < 2; mi++)
                #pragma unroll
                for (int n = 0; n < 4; n++)
                    #pragma unroll
                    for (int e = 0; e < 4; e++) s[mi][n][e] = 0.f;

            #pragma unroll
            for (int ks = 0; ks < 8; ks++) {
                uint32_t bfr[4][2];
                #pragma unroll
                for (int n = 0; n < 4; n++) {
                    const float* p = Ks + (j0 + (hn * 4 + n) * 8 + gr) * KSTR + ks * 8 + ctl;
                    bfr[n][0] = __float_as_uint(p[0]);
                    bfr[n][1] = __float_as_uint(p[4]);
                }
                #pragma unroll
                for (int mi = 0; mi < 2; mi++)
                    #pragma unroll
                    for (int n = 0; n < 4; n++)
                        mma_tf32(s[mi][n], aq[mi][ks], bfr[n]);
            }

            #pragma unroll
            for (int mi = 0; mi < 2; mi++) {
                const int rowb = r0 + mi * 16 + gr;
                #pragma unroll
                for (int n = 0; n < 4; n++) {
                    const int nt  = hn * 4 + n;
                    const int col = j0 + nt * 8 + 2 * ctl;
                    float p00 = (col     <= rowb)     ? tf32r(__expf(s[mi][n][0])) : 0.f;
                    float p01 = (col + 1 <= rowb)     ? tf32r(__expf(s[mi][n][1])) : 0.f;
                    float p10 = (col     <= rowb + 8) ? tf32r(__expf(s[mi][n][2])) : 0.f;
                    float p11 = (col + 1 <= rowb + 8) ? tf32r(__expf(s[mi][n][3])) : 0.f;
                    lsum[mi][0] += p00 + p01;
                    lsum[mi][1] += p10 + p11;
                    float2 v0 = {p00, p01}, v1 = {p10, p11};
                    *(float2*)(Pw + (mi * 16 + gr) * PSTR + nt * 8 + 2 * ctl)     = v0;
                    *(float2*)(Pw + (mi * 16 + 8 + gr) * PSTR + nt * 8 + 2 * ctl) = v1;
                }
            }
        }
        __syncwarp();

        #pragma unroll
        for (int ks = 0; ks < 8; ks++) {
            uint32_t ap[2][4];
            #pragma unroll
            for (int mi = 0; mi < 2; mi++) {
                const float* p = Pw + (mi * 16 + gr) * PSTR + ks * 8 + ctl;
                ap[mi][0] = __float_as_uint(p[0]);
                ap[mi][1] = __float_as_uint(p[8 * PSTR]);
                ap[mi][2] = __float_as_uint(p[4]);
                ap[mi][3] = __float_as_uint(p[8 * PSTR + 4]);
            }
            #pragma unroll
            for (int nt = 0; nt < 8; nt++) {
                uint32_t bv2[2];
                const float* p = Vs + (j0 + ks * 8 + ctl) * KSTR + nt * 8 + gr;
                bv2[0] = __float_as_uint(p[0]);
                bv2[1] = __float_as_uint(p[4 * KSTR]);
                #pragma unroll
                for (int mi = 0; mi < 2; mi++)
                    mma_tf32(oacc[mi][nt], ap[mi], bv2);
            }
        }
    }

    float inv[2][2];
    #pragma unroll
    for (int mi = 0; mi < 2; mi++)
        #pragma unroll
        for (int hf = 0; hf < 2; hf++) {
            float l = lsum[mi][hf];
            l += __shfl_xor_sync(0xffffffff, l, 1);
            l += __shfl_xor_sync(0xffffffff, l, 2);
            inv[mi][hf] = 1.f / l;
        }

    // epilogue: write g_y in k-interleaved order.
    // thread's pair (d = nt*8 + 2ctl, +1) -> positions nt*8 + q, nt*8 + q + 2
    // with q = (ctl&1)*4 + (ctl>>1).
    const int q = (ctl & 1) * 4 + (ctl >> 1);
    #pragma unroll
    for (int mi = 0; mi < 2; mi++)
        #pragma unroll
        for (int hf = 0; hf < 2; hf++) {
            int trow = r0 + mi * 16 + gr + 8 * hf;
            float* yp = g_y + (size_t)(b * Tn + trow) * (Hn * Cn * HD) + (h * Cn + c) * HD;
            #pragma unroll
            for (int nt = 0; nt < 8; nt++) {
                yp[nt * 8 + q]     = tf32r(oacc[mi][nt][hf * 2 + 0] * inv[mi][hf]);
                yp[nt * 8 + q + 2] = tf32r(oacc[mi][nt][hf * 2 + 1] * inv[mi][hf]);
            }
        }
}

// ---------------------------------------------------------------------------
extern "C" void kernel_launch(void* const* d_in, const int* in_sizes, int n_in,
                              void* d_out, int out_size)
{
    const float* x  = (const float*)d_in[0];
    const float* Wq = (const float*)d_in[1];
    const float* bq = (const float*)d_in[2];
    const float* Wk = (const float*)d_in[3];
    const float* bk = (const float*)d_in[4];
    const float* Wv = (const float*)d_in[5];
    const float* bv = (const float*)d_in[6];
    const float* Wp = (const float*)d_in[7];
    const float* bp = (const float*)d_in[8];
    float* out = (float*)d_out;

    cudaFuncSetAttribute(attn_kernel, cudaFuncAttributeMaxDynamicSharedMemorySize,
                         ATTN_SMEM_BYTES);

    round_x_kernel<<<(NTOK * En / 8) / 256, 256>>>(x);
    round_w_kernel<<<(4 * En * En / 8) / 256, 256>>>(Wq, Wk, Wv, Wp);
    qkv_mma<<<dim3(NTOK / 128, 12), 256>>>(bq, bk, bv);
    attn_kernel<<<NHEADS, 256, ATTN_SMEM_BYTES>>>();
    proj_mma<<<dim3(NTOK / 128, 4), 256>>>(bp, out);
}

// round 12
// speedup vs baseline: 1.0179x; 1.0179x over previous
#include <cuda_runtime.h>
#include <cstdint>

#define Bn 16
#define Tn 256
#define Cn 6
#define En 512
#define Hn 8
#define HD 64
#define NTOK (Bn*Tn*Cn)      // 24576
#define NHEADS (Bn*Hn*Cn)    // 768

// ---- device-global scratch (no allocations allowed) ----
// g_xr, g_wr: k-interleaved (perfect-shuffle per 8-block) tf32.
// g_q/g_k/g_v/g_y: plain layout, tf32-rounded values.
__device__ float g_q[(size_t)NHEADS * Tn * HD];
__device__ float g_k[(size_t)NHEADS * Tn * HD];
__device__ float g_v[(size_t)NHEADS * Tn * HD];
__device__ float g_y[(size_t)NTOK * En];
__device__ float g_xr[(size_t)NTOK * En];
__device__ float g_wr[(size_t)4 * En * En];

// ---------------------------------------------------------------------------
__device__ __forceinline__ float tf32r(float x) {
    uint32_t u;
    asm("cvt.rna.tf32.f32 %0, %1;" : "=r"(u) : "f"(x));
    return __uint_as_float(u);
}

__device__ __forceinline__ void cpasync16(void* smem_dst, const void* gsrc) {
    uint32_t s = (uint32_t)__cvta_generic_to_shared(smem_dst);
    asm volatile("cp.async.ca.shared.global [%0], [%1], 16;\n" :: "r"(s), "l"(gsrc));
}

__device__ __forceinline__ void mma_tf32(float c[4], const uint32_t a[4], const uint32_t b[2]) {
    asm volatile(
        "mma.sync.aligned.m16n8k8.row.col.f32.tf32.tf32.f32 "
        "{%0,%1,%2,%3}, {%4,%5,%6,%7}, {%8,%9}, {%0,%1,%2,%3};"
        : "+f"(c[0]), "+f"(c[1]), "+f"(c[2]), "+f"(c[3])
        : "r"(a[0]), "r"(a[1]), "r"(a[2]), "r"(a[3]), "r"(b[0]), "r"(b[1]));
}

// ---------------------------------------------------------------------------
// Prepass (single launch): round to tf32 AND perfect-shuffle each 8-float
// k-block: out[8b + 0..7] = in[8b + {0,4,1,5,2,6,3,7}], so GEMM fragment
// pairs (k, k+4) are adjacent -> LDS.64 fragment loads.
// ---------------------------------------------------------------------------
__device__ __forceinline__ void shuffle_store8(float* dst, float4 lo, float4 hi) {
    float4 o0, o1;
    o0.x = tf32r(lo.x); o0.y = tf32r(hi.x); o0.z = tf32r(lo.y); o0.w = tf32r(hi.y);
    o1.x = tf32r(lo.z); o1.y = tf32r(hi.z); o1.z = tf32r(lo.w); o1.w = tf32r(hi.w);
    *(float4*)dst       = o0;
    *(float4*)(dst + 4) = o1;
}

#define NX8 (NTOK * En / 8)          // 1572864 x-blocks
#define NW8 (4 * En * En / 8)        // 131072 w-blocks

__global__ void round_all_kernel(const float* __restrict__ x,
                                 const float* __restrict__ Wq, const float* __restrict__ Wk,
                                 const float* __restrict__ Wv, const float* __restrict__ Wp) {
    int i = blockIdx.x * 256 + threadIdx.x;
    if (i < NX8) {
        float4 lo = ((const float4*)x)[i * 2];
        float4 hi = ((const float4*)x)[i * 2 + 1];
        shuffle_store8(g_xr + (size_t)i * 8, lo, hi);
    } else {
        int j = i - NX8;
        int w = j >> 15;
        int off = j & 32767;
        const float* src = (w == 0) ? Wq : (w == 1) ? Wk : (w == 2) ? Wv : Wp;
        float4 lo = ((const float4*)src)[off * 2];
        float4 hi = ((const float4*)src)[off * 2 + 1];
        shuffle_store8(g_wr + (size_t)j * 8, lo, hi);
    }
}

// ---------------------------------------------------------------------------
// GEMM cores. 128x128 CTA tile, 8 warps (2M x 4N), warp tile 64x32, BK=16,
// double-buffered cp.async.
//  - interleaved operands: smem stride 24 (==8 mod 32), LDS.64 frags.
//  - plain operands:       smem stride 20 (==20 mod 32), LDS.32 frags.
// Both verified conflict-free.
// ---------------------------------------------------------------------------
#define SSI 24     // interleaved stride
#define SSP 20     // plain stride
#define BK  16

__device__ __forceinline__ void load_tile_s(float* dst, const float* gsrc,
                                            int stride, int k0, int tid) {
    #pragma unroll
    for (int it = 0; it < 2; it++) {
        int idx = it * 256 + tid;          // 0..511
        int m   = idx >> 2;
        int kc  = (idx & 3) * 4;
        cpasync16(dst + m * stride + kc, gsrc + (size_t)m * En + k0 + kc);
    }
}

// Both operands interleaved (qkv).
__device__ __forceinline__ void compute_tile_ii(const float* As, const float* Bs,
                                                float acc[4][4][4],
                                                int wm, int wn, int gr, int ctl) {
    #pragma unroll
    for (int g2 = 0; g2 < 2; g2++) {
        const int ko = g2 * 8 + 2 * ctl;
        uint32_t a[4][4], b[4][2];
        #pragma unroll
        for (int mi = 0; mi < 4; mi++) {
            const float* p = As + (wm * 64 + mi * 16 + gr) * SSI + ko;
            float2 lo = *(const float2*)p;
            float2 hi = *(const float2*)(p + 8 * SSI);
            a[mi][0] = __float_as_uint(lo.x);
            a[mi][2] = __float_as_uint(lo.y);
            a[mi][1] = __float_as_uint(hi.x);
            a[mi][3] = __float_as_uint(hi.y);
        }
        #pragma unroll
        for (int ni = 0; ni < 4; ni++) {
            const float* p = Bs + (wn * 32 + ni * 8 + gr) * SSI + ko;
            float2 v = *(const float2*)p;
            b[ni][0] = __float_as_uint(v.x);
            b[ni][1] = __float_as_uint(v.y);
        }
        #pragma unroll
        for (int mi = 0; mi < 4; mi++)
            #pragma unroll
            for (int ni = 0; ni < 4; ni++)
                mma_tf32(acc[mi][ni], a[mi], b[ni]);
    }
}

// A plain, B interleaved (proj).
__device__ __forceinline__ void compute_tile_pi(const float* As, const float* Bs,
                                                float acc[4][4][4],
                                                int wm, int wn, int gr, int ctl) {
    #pragma unroll
    for (int g2 = 0; g2 < 2; g2++) {
        uint32_t a[4][4], b[4][2];
        #pragma unroll
        for (int mi = 0; mi < 4; mi++) {
            const float* p = As + (wm * 64 + mi * 16 + gr) * SSP + g2 * 8 + ctl;
            a[mi][0] = __float_as_uint(p[0]);
            a[mi][1] = __float_as_uint(p[8 * SSP]);
            a[mi][2] = __float_as_uint(p[4]);
            a[mi][3] = __float_as_uint(p[8 * SSP + 4]);
        }
        #pragma unroll
        for (int ni = 0; ni < 4; ni++) {
            const float* p = Bs + (wn * 32 + ni * 8 + gr) * SSI + g2 * 8 + 2 * ctl;
            float2 v = *(const float2*)p;
            b[ni][0] = __float_as_uint(v.x);
            b[ni][1] = __float_as_uint(v.y);
        }
        #pragma unroll
        for (int mi = 0; mi < 4; mi++)
            #pragma unroll
            for (int ni = 0; ni < 4; ni++)
                mma_tf32(acc[mi][ni], a[mi], b[ni]);
    }
}

#define GEMM_MAINLOOP(gA, gB, SA, SB, CT)                              \
    load_tile_s(As[0], gA, SA, 0, tid);                                \
    load_tile_s(Bs[0], gB, SB, 0, tid);                                \
    asm volatile("cp.async.commit_group;\n" ::);                       \
    _Pragma("unroll 1")                                                \
    for (int kt = 0; kt < En / BK; kt++) {                             \
        if (kt + 1 < En / BK) {                                        \
            load_tile_s(As[(kt + 1) & 1], gA, SA, (kt + 1) * BK, tid); \
            load_tile_s(Bs[(kt + 1) & 1], gB, SB, (kt + 1) * BK, tid); \
            asm volatile("cp.async.commit_group;\n" ::);               \
            asm volatile("cp.async.wait_group 1;\n" ::);               \
        } else {                                                       \
            asm volatile("cp.async.wait_group 0;\n" ::);               \
        }                                                              \
        __syncthreads();                                               \
        CT(As[kt & 1], Bs[kt & 1], acc, wm, wn, gr, ctl);              \
        __syncthreads();                                               \
    }

// ---------------------------------------------------------------------------
// QKV: y = x @ W^T + b, scattered into per-head (b,h,c,t,d), tf32-rounded.
// grid = (192, 12): y [0,4)=Q, [4,8)=K, [8,12)=V
// ---------------------------------------------------------------------------
__global__ void __launch_bounds__(256, 2)
qkv_mma(const float* __restrict__ bq, const float* __restrict__ bk,
        const float* __restrict__ bv)
{
    __shared__ float As[2][128 * SSI];
    __shared__ float Bs[2][128 * SSI];

    const int tid = threadIdx.x, lane = tid & 31, warp = tid >> 5;
    const int wm = warp & 1, wn = warp >> 1;
    const int gr = lane >> 2, ctl = lane & 3;

    const int m0 = blockIdx.x * 128;
    const int mm = blockIdx.y >> 2;
    const int f0 = (blockIdx.y & 3) * 128;

    const float* gA = g_xr + (size_t)m0 * En;
    const float* gB = g_wr + (size_t)mm * En * En + (size_t)f0 * En;
    const float* bias = (mm == 0) ? bq : (mm == 1) ? bk : bv;
    float* gout = (mm == 0) ? g_q : (mm == 1) ? g_k : g_v;

    float acc[4][4][4];
    #pragma unroll
    for (int i = 0; i < 4; i++)
        #pragma unroll
        for (int j = 0; j < 4; j++)
            #pragma unroll
            for (int l = 0; l < 4; l++) acc[i][j][l] = 0.f;

    GEMM_MAINLOOP(gA, gB, SSI, SSI, compute_tile_ii)

    const int fbase = f0 + wn * 32;
    #pragma unroll
    for (int mi = 0; mi < 4; mi++) {
        #pragma unroll
        for (int half = 0; half < 2; half++) {
            int r = m0 + wm * 64 + mi * 16 + gr + half * 8;
            int b = r / (Tn * Cn);
            int rem = r - b * (Tn * Cn);
            int t = rem / Cn;
            int cc = rem - t * Cn;
            #pragma unroll
            for (int ni = 0; ni < 4; ni++) {
                int f = fbase + ni * 8 + 2 * ctl;
                int h = f >> 6, d = f & 63;
                float2 o;
                o.x = tf32r(acc[mi][ni][half * 2 + 0] + bias[f]);
                o.y = tf32r(acc[mi][ni][half * 2 + 1] + bias[f + 1]);
                float* dst = gout + ((((size_t)b * Hn + h) * Cn + cc) * Tn + t) * HD + d;
                *(float2*)dst = o;
            }
        }
    }
}

// ---------------------------------------------------------------------------
// Output projection: out = g_y(plain) @ Wp(interleaved)^T + bp.  grid=(192,4)
// ---------------------------------------------------------------------------
__global__ void __launch_bounds__(256, 2)
proj_mma(const float* __restrict__ bp, float* __restrict__ out)
{
    __shared__ float As[2][128 * SSP];
    __shared__ float Bs[2][128 * SSI];

    const int tid = threadIdx.x, lane = tid & 31, warp = tid >> 5;
    const int wm = warp & 1, wn = warp >> 1;
    const int gr = lane >> 2, ctl = lane & 3;

    const int m0 = blockIdx.x * 128;
    const int f0 = blockIdx.y * 128;

    const float* gA = g_y + (size_t)m0 * En;
    const float* gB = g_wr + (size_t)3 * En * En + (size_t)f0 * En;

    float acc[4][4][4];
    #pragma unroll
    for (int i = 0; i < 4; i++)
        #pragma unroll
        for (int j = 0; j < 4; j++)
            #pragma unroll
            for (int l = 0; l < 4; l++) acc[i][j][l] = 0.f;

    GEMM_MAINLOOP(gA, gB, SSP, SSI, compute_tile_pi)

    #pragma unroll
    for (int mi = 0; mi < 4; mi++) {
        #pragma unroll
        for (int half = 0; half < 2; half++) {
            int r = m0 + wm * 64 + mi * 16 + gr + half * 8;
            #pragma unroll
            for (int ni = 0; ni < 4; ni++) {
                int col = f0 + wn * 32 + ni * 8 + 2 * ctl;
                float2 o;
                o.x = acc[mi][ni][half * 2 + 0] + bp[col];
                o.y = acc[mi][ni][half * 2 + 1] + bp[col + 1];
                *(float2*)(out + (size_t)r * En + col) = o;
            }
        }
    }
}

// ---------------------------------------------------------------------------
// MMA attention (round-4 structure, rna-rounded P, plain coalesced epilogue).
// 1 CTA per head, 8 warps; warp w owns query rows 32w..32w+31, does w/2+1 tiles.
// ---------------------------------------------------------------------------
#define KSTR 68
#define PSTR 72
#define ATTN_SMEM_BYTES ((2 * Tn * KSTR + 8 * 32 * PSTR) * 4)   // 212992

__global__ void __launch_bounds__(256, 1)
attn_kernel()
{
    extern __shared__ float smem[];
    float* Ks = smem;                  // [256][KSTR]
    float* Vs = smem + Tn * KSTR;      // [256][KSTR]

    const int hh = blockIdx.x;
    const int c  = hh % Cn;
    const int bh = hh / Cn;
    const int h  = bh % Hn;
    const int b  = bh / Hn;

    const float* qp = g_q + (size_t)hh * Tn * HD;
    const float* kp = g_k + (size_t)hh * Tn * HD;
    const float* vp = g_v + (size_t)hh * Tn * HD;

    const int tid  = threadIdx.x;
    const int lane = tid & 31, warp = tid >> 5;
    const int gr   = lane >> 2, ctl = lane & 3;

    float* Pw = smem + 2 * Tn * KSTR + warp * 32 * PSTR;  // [32][PSTR]

    // ---- load full K and V into smem ----
    #pragma unroll
    for (int it = 0; it < 16; it++) {
        int idx = it * 256 + tid;
        int row = idx >> 4;
        int c4  = (idx & 15) * 4;
        cpasync16(Ks + row * KSTR + c4, kp + row * HD + c4);
        cpasync16(Vs + row * KSTR + c4, vp + row * HD + c4);
    }
    asm volatile("cp.async.commit_group;\n" ::);

    const int r0 = warp * 32;
    asm volatile("cp.async.wait_group 0;\n" ::);
    __syncthreads();

    // ---- stage Q (scaled by exact 2^-3) into Pw, build A-fragments ----
    #pragma unroll
    for (int it = 0; it < 16; it++) {
        int idx = it * 32 + lane;
        int row = idx >> 4;
        int c4  = (idx & 15) * 4;
        float4 v4 = *(const float4*)(qp + (size_t)(r0 + row) * HD + c4);
        v4.x *= 0.125f; v4.y *= 0.125f; v4.z *= 0.125f; v4.w *= 0.125f;
        *(float4*)(Pw + row * PSTR + c4) = v4;
    }
    __syncwarp();

    uint32_t aq[2][8][4];
    #pragma unroll
    for (int mi = 0; mi < 2; mi++)
        #pragma unroll
        for (int ks = 0; ks < 8; ks++) {
            const float* p = Pw + (mi * 16 + gr) * PSTR + ks * 8 + ctl;
            aq[mi][ks][0] = __float_as_uint(p[0]);
            aq[mi][ks][1] = __float_as_uint(p[8 * PSTR]);
            aq[mi][ks][2] = __float_as_uint(p[4]);
            aq[mi][ks][3] = __float_as_uint(p[8 * PSTR + 4]);
        }

    float oacc[2][8][4];
    #pragma unroll
    for (int mi = 0; mi < 2; mi++)
        #pragma unroll
        for (int nt = 0; nt < 8; nt++)
            #pragma unroll
            for (int e = 0; e < 4; e++) oacc[mi][nt][e] = 0.f;
    float lsum[2][2] = {{0.f, 0.f}, {0.f, 0.f}};

    const int ntiles = (warp >> 1) + 1;

    #pragma unroll 1
    for (int jt = 0; jt < ntiles; jt++) {
        const int j0 = jt * 64;
        __syncwarp();

        #pragma unroll
        for (int hn = 0; hn < 2; hn++) {
            float s[2][4][4];
            #pragma unroll
            for (int mi = 0; mi < 2; mi++)
                #pragma unroll
                for (int n = 0; n < 4; n++)
                    #pragma unroll
                    for (int e = 0; e < 4; e++) s[mi][n][e] = 0.f;

            #pragma unroll
            for (int ks = 0; ks < 8; ks++) {
                uint32_t bfr[4][2];
                #pragma unroll
                for (int n = 0; n < 4; n++) {
                    const float* p = Ks + (j0 + (hn * 4 + n) * 8 + gr) * KSTR + ks * 8 + ctl;
                    bfr[n][0] = __float_as_uint(p[0]);
                    bfr[n][1] = __float_as_uint(p[4]);
                }
                #pragma unroll
                for (int mi = 0; mi < 2; mi++)
                    #pragma unroll
                    for (int n = 0; n < 4; n++)
                        mma_tf32(s[mi][n], aq[mi][ks], bfr[n]);
            }

            #pragma unroll
            for (int mi = 0; mi < 2; mi++) {
                const int rowb = r0 + mi * 16 + gr;
                #pragma unroll
                for (int n = 0; n < 4; n++) {
                    const int nt  = hn * 4 + n;
                    const int col = j0 + nt * 8 + 2 * ctl;
                    float p00 = (col     <= rowb)     ? tf32r(__expf(s[mi][n][0])) : 0.f;
                    float p01 = (col + 1 <= rowb)     ? tf32r(__expf(s[mi][n][1])) : 0.f;
                    float p10 = (col     <= rowb + 8) ? tf32r(__expf(s[mi][n][2])) : 0.f;
                    float p11 = (col + 1 <= rowb + 8) ? tf32r(__expf(s[mi][n][3])) : 0.f;
                    lsum[mi][0] += p00 + p01;
                    lsum[mi][1] += p10 + p11;
                    float2 v0 = {p00, p01}, v1 = {p10, p11};
                    *(float2*)(Pw + (mi * 16 + gr) * PSTR + nt * 8 + 2 * ctl)     = v0;
                    *(float2*)(Pw + (mi * 16 + 8 + gr) * PSTR + nt * 8 + 2 * ctl) = v1;
                }
            }
        }
        __syncwarp();

        #pragma unroll
        for (int ks = 0; ks < 8; ks++) {
            uint32_t ap[2][4];
            #pragma unroll
            for (int mi = 0; mi < 2; mi++) {
                const float* p = Pw + (mi * 16 + gr) * PSTR + ks * 8 + ctl;
                ap[mi][0] = __float_as_uint(p[0]);
                ap[mi][1] = __float_as_uint(p[8 * PSTR]);
                ap[mi][2] = __float_as_uint(p[4]);
                ap[mi][3] = __float_as_uint(p[8 * PSTR + 4]);
            }
            #pragma unroll
            for (int nt = 0; nt < 8; nt++) {
                uint32_t bv2[2];
                const float* p = Vs + (j0 + ks * 8 + ctl) * KSTR + nt * 8 + gr;
                bv2[0] = __float_as_uint(p[0]);
                bv2[1] = __float_as_uint(p[4 * KSTR]);
                #pragma unroll
                for (int mi = 0; mi < 2; mi++)
                    mma_tf32(oacc[mi][nt], ap[mi], bv2);
            }
        }
    }

    float inv[2][2];
    #pragma unroll
    for (int mi = 0; mi < 2; mi++)
        #pragma unroll
        for (int hf = 0; hf < 2; hf++) {
            float l = lsum[mi][hf];
            l += __shfl_xor_sync(0xffffffff, l, 1);
            l += __shfl_xor_sync(0xffffffff, l, 2);
            inv[mi][hf] = 1.f / l;
        }

    // plain coalesced epilogue (g_y plain layout)
    #pragma unroll
    for (int mi = 0; mi < 2; mi++)
        #pragma unroll
        for (int hf = 0; hf < 2; hf++) {
            int trow = r0 + mi * 16 + gr + 8 * hf;
            float* yp = g_y + (size_t)(b * Tn + trow) * (Hn * Cn * HD) + (h * Cn + c) * HD;
            #pragma unroll
            for (int nt = 0; nt < 8; nt++) {
                float2 o;
                o.x = tf32r(oacc[mi][nt][hf * 2 + 0] * inv[mi][hf]);
                o.y = tf32r(oacc[mi][nt][hf * 2 + 1] * inv[mi][hf]);
                *(float2*)(yp + nt * 8 + 2 * ctl) = o;
            }
        }
}

// ---------------------------------------------------------------------------
extern "C" void kernel_launch(void* const* d_in, const int* in_sizes, int n_in,
                              void* d_out, int out_size)
{
    const float* x  = (const float*)d_in[0];
    const float* Wq = (const float*)d_in[1];
    const float* bq = (const float*)d_in[2];
    const float* Wk = (const float*)d_in[3];
    const float* bk = (const float*)d_in[4];
    const float* Wv = (const float*)d_in[5];
    const float* bv = (const float*)d_in[6];
    const float* Wp = (const float*)d_in[7];
    const float* bp = (const float*)d_in[8];
    float* out = (float*)d_out;

    cudaFuncSetAttribute(attn_kernel, cudaFuncAttributeMaxDynamicSharedMemorySize,
                         ATTN_SMEM_BYTES);

    round_all_kernel<<<(NX8 + NW8) / 256, 256>>>(x, Wq, Wk, Wv, Wp);
    qkv_mma<<<dim3(NTOK / 128, 12), 256>>>(bq, bk, bv);
    attn_kernel<<<NHEADS, 256, ATTN_SMEM_BYTES>>>();
    proj_mma<<<dim3(NTOK / 128, 4), 256>>>(bp, out);
}